// round 16
// baseline (speedup 1.0000x reference)
#include <cuda_runtime.h>

// rate_RNN_mante: T=1000, B=64, I=4, H=1024, O=2, P=16
// Low-rank recurrence: r @ Wr^T = (r @ pout) @ (l*pin)^T
// One persistent CTA per batch element; mem state in registers.
// R16 = R12 (best measured, re-benched 527.6/528.4us) + phase-1 accumulation
//       tree-split: two 2-deep FMA chains per part[j] instead of one 4-deep
//       chain, shortening the tanh->butterfly critical-path segment.
//       (Session law: chain cuts pay ~1:1, slot additions are free.)

#define T_STEPS 1000
#define BATCH   64
#define I_DIM   4
#define H_DIM   1024
#define O_DIM   2
#define P_DIM   16
#define HPT     4                 // h-rows per thread
#define NTHREADS 256              // H_DIM / HPT
#define NWARPS  (NTHREADS / 32)
#define NRED    18                // 16 z-values + 2 y-values
#define PROW    36                // 32 z-partial cols + 4 y-partial cols

__device__ __forceinline__ float fast_tanh(float x) {
    float r;
    asm("tanh.approx.f32 %0, %1;" : "=f"(r) : "f"(x));
    return r;
}
__device__ __forceinline__ float shfl_xor_f(float v, int off) {
    return __shfl_xor_sync(0xffffffffu, v, off);
}

__global__ __launch_bounds__(NTHREADS, 1)
void rate_rnn_kernel(const float* __restrict__ x,     // (T,B,I,1)
                     const float* __restrict__ Win,   // (H,I)
                     const float* __restrict__ Wout,  // (O,H)
                     const float* __restrict__ pin,   // (H,P)
                     const float* __restrict__ pout,  // (H,P)
                     const float* __restrict__ l,     // (P,)
                     float* __restrict__ y)           // (T,B,O,1)
{
    const int b    = blockIdx.x;
    const int tid  = threadIdx.x;
    const int lane = tid & 31;
    const int warp = tid >> 5;

    __shared__ __align__(16) float pbuf[NWARPS][PROW];  // per-warp partials
    __shared__ __align__(16) float zbuf[P_DIM];         // broadcast z

    const float lm = 0.95122942450071400910f;  // exp(-DT/TAUM) = exp(-0.05)
    const float om = 1.0f - lm;

    // butterfly lane roles
    const bool hi16 = (lane & 16) != 0;
    const bool hi8  = (lane & 8)  != 0;
    const bool hi4  = (lane & 4)  != 0;
    const bool hi2  = (lane & 2)  != 0;
    const bool wyp  = (lane & 15) < 2;            // y-partial writer lanes 0,1,16,17
    const int  ycol = 32 + ((lane >> 4) << 1) + (lane & 1);  // y-partial column

    float lvec[P_DIM];
    #pragma unroll
    for (int p = 0; p < P_DIM; p++) lvec[p] = l[p];

    float mem[HPT];
    float win[HPT][I_DIM];     // om * Win (folded)
    float m[HPT][NRED];        // [pout (16) | Wout^T (2)]
    float lp[HPT][P_DIM];      // om * l * pin (folded)

    #pragma unroll
    for (int k = 0; k < HPT; k++) {
        const int h = tid + k * NTHREADS;
        mem[k] = 0.0f;
        #pragma unroll
        for (int i = 0; i < I_DIM; i++) win[k][i] = om * Win[h * I_DIM + i];
        #pragma unroll
        for (int p = 0; p < P_DIM; p++) {
            m[k][p]  = pout[h * P_DIM + p];
            lp[k][p] = om * lvec[p] * pin[h * P_DIM + p];
        }
        m[k][16] = Wout[h];           // Wout[0][h]
        m[k][17] = Wout[H_DIM + h];   // Wout[1][h]
    }

    const float4* xp = reinterpret_cast<const float4*>(x) + b;
    float4 xc = __ldg(xp);   // t = 0
    float4 xn = xc;

    // Iteration t: r_t = tanh(mem_t); y[t-1] = Wout.r_t; advance mem (t < T).
    for (int t = 0; t <= T_STEPS; t++) {
        {   // clamped prefetch of next x
            int tn = t + 1; if (tn > T_STEPS - 1) tn = T_STEPS - 1;
            xn = __ldg(xp + tn * BATCH);
        }

        // ---- phase 1: tanh + tree-split accumulation (two 2-deep chains) ----
        const float r0 = fast_tanh(mem[0]);
        const float r1 = fast_tanh(mem[1]);
        const float r2 = fast_tanh(mem[2]);
        const float r3 = fast_tanh(mem[3]);

        float part[NRED];
        #pragma unroll
        for (int j = 0; j < NRED; j++) {
            float pa = r0 * m[0][j];
            pa = fmaf(r1, m[1][j], pa);
            float pb = r2 * m[2][j];
            pb = fmaf(r3, m[3][j], pb);
            part[j] = pa + pb;
        }

        // ---- z-independent drive, hoisted off the post-bar2 chain ----
        float a0r[HPT];
        #pragma unroll
        for (int k = 0; k < HPT; k++) {
            float a = lm * mem[k];
            a = fmaf(win[k][0], xc.x, a);
            a = fmaf(win[k][1], xc.y, a);
            a = fmaf(win[k][2], xc.z, a);
            a = fmaf(win[k][3], xc.w, a);
            a0r[k] = a;
        }

        // ---- split-butterfly z: rounds 16/8/4/2 (4 deep, no final xor-1) ----
        float v8[8];
        #pragma unroll
        for (int i = 0; i < 8; i++) {
            float send = hi16 ? part[i] : part[i + 8];
            float keep = hi16 ? part[i + 8] : part[i];
            v8[i] = keep + shfl_xor_f(send, 16);
        }
        float v4[4];
        #pragma unroll
        for (int i = 0; i < 4; i++) {
            float send = hi8 ? v8[i] : v8[i + 4];
            float keep = hi8 ? v8[i + 4] : v8[i];
            v4[i] = keep + shfl_xor_f(send, 8);
        }
        float v2[2];
        #pragma unroll
        for (int i = 0; i < 2; i++) {
            float send = hi4 ? v4[i] : v4[i + 2];
            float keep = hi4 ? v4[i + 2] : v4[i];
            v2[i] = keep + shfl_xor_f(send, 4);
        }
        float v1;
        {
            float send = hi2 ? v2[0] : v2[1];
            float keep = hi2 ? v2[1] : v2[0];
            v1 = keep + shfl_xor_f(send, 2);
        }
        // lanes 2j,2j+1 hold the two partials of z[j]

        // ---- y: split + rounds 8/4/2 (4 deep, no final xor-1) ----
        float wv;
        {
            float send = hi16 ? part[16] : part[17];
            float keep = hi16 ? part[17] : part[16];
            wv = keep + shfl_xor_f(send, 16);
        }
        wv += shfl_xor_f(wv, 8);
        wv += shfl_xor_f(wv, 4);
        wv += shfl_xor_f(wv, 2);
        // lane L holds mod-2-class partial of y[16+(L>>4)]

        pbuf[warp][lane] = v1;            // 32 z-partial cols, coalesced
        if (wyp) pbuf[warp][ycol] = wv;   // lanes 0,1,16,17 -> cols 32..35
        __syncthreads();

        // ---- phase 2: sum 16 partials per value (8 float2 loads + tree) ----
        if (tid < NRED) {
            const int c = (tid < P_DIM) ? (2 * tid) : (32 + 2 * (tid - P_DIM));
            float2 q0 = *reinterpret_cast<const float2*>(&pbuf[0][c]);
            float2 q1 = *reinterpret_cast<const float2*>(&pbuf[1][c]);
            float2 q2 = *reinterpret_cast<const float2*>(&pbuf[2][c]);
            float2 q3 = *reinterpret_cast<const float2*>(&pbuf[3][c]);
            float2 q4 = *reinterpret_cast<const float2*>(&pbuf[4][c]);
            float2 q5 = *reinterpret_cast<const float2*>(&pbuf[5][c]);
            float2 q6 = *reinterpret_cast<const float2*>(&pbuf[6][c]);
            float2 q7 = *reinterpret_cast<const float2*>(&pbuf[7][c]);
            float sx = ((q0.x + q1.x) + (q2.x + q3.x)) + ((q4.x + q5.x) + (q6.x + q7.x));
            float sy = ((q0.y + q1.y) + (q2.y + q3.y)) + ((q4.y + q5.y) + (q6.y + q7.y));
            float s  = sx + sy;
            if (tid < P_DIM) {
                zbuf[tid] = s;
            } else if (t > 0) {
                y[((t - 1) * BATCH + b) * O_DIM + (tid - P_DIM)] = s;
            }
        }
        __syncthreads();

        if (t == T_STEPS) break;

        // ---- phase 3: z feedback only (drive already in a0r) ----
        const float4* zv = reinterpret_cast<const float4*>(zbuf);
        const float4 z0 = zv[0], z1 = zv[1], z2 = zv[2], z3 = zv[3];

        #pragma unroll
        for (int k = 0; k < HPT; k++) {
            float a1 = z0.x * lp[k][0];
            a1 = fmaf(z0.y, lp[k][1],  a1);
            a1 = fmaf(z0.z, lp[k][2],  a1);
            a1 = fmaf(z0.w, lp[k][3],  a1);
            a1 = fmaf(z1.x, lp[k][4],  a1);
            a1 = fmaf(z1.y, lp[k][5],  a1);
            a1 = fmaf(z1.z, lp[k][6],  a1);
            a1 = fmaf(z1.w, lp[k][7],  a1);

            float a2 = z2.x * lp[k][8];
            a2 = fmaf(z2.y, lp[k][9],  a2);
            a2 = fmaf(z2.z, lp[k][10], a2);
            a2 = fmaf(z2.w, lp[k][11], a2);
            a2 = fmaf(z3.x, lp[k][12], a2);
            a2 = fmaf(z3.y, lp[k][13], a2);
            a2 = fmaf(z3.z, lp[k][14], a2);
            a2 = fmaf(z3.w, lp[k][15], a2);

            mem[k] = a0r[k] + (a1 + a2);
        }
        xc = xn;
    }
}

extern "C" void kernel_launch(void* const* d_in, const int* in_sizes, int n_in,
                              void* d_out, int out_size)
{
    const float* x    = (const float*)d_in[0];
    const float* Win  = (const float*)d_in[1];
    const float* Wout = (const float*)d_in[2];
    const float* pin  = (const float*)d_in[3];
    const float* pout = (const float*)d_in[4];
    const float* l    = (const float*)d_in[5];
    float* y = (float*)d_out;

    rate_rnn_kernel<<<BATCH, NTHREADS>>>(x, Win, Wout, pin, pout, l, y);
}

// round 17
// speedup vs baseline: 1.0339x; 1.0339x over previous
#include <cuda_runtime.h>

// rate_RNN_mante: T=1000, B=64, I=4, H=1024, O=2, P=16
// Low-rank recurrence: r @ Wr^T = (r @ pout) @ (l*pin)^T
// One persistent CTA per batch element; mem state in registers.
// R17 = FINAL: R12 verbatim (measured 527.6 / 528.4 us across two runs).
//   Architecture: scalar FMA, central 2-barrier structure, 4-round split
//   butterfly (2 partials/value), hoisted z-independent drive, tanh.approx.
//   12-variant search ledger: duration is pinned (~965 cyc/step) by the
//   semantically-required per-step z synchronization; only chain cuts that
//   preserve issue order ever helped (R11, R12); slot, barrier-protocol,
//   broadcast-mechanism, and reduction-depth changes were all flat or
//   negative. R16's tanh-hoist regression confirmed the issue-order caveat.

#define T_STEPS 1000
#define BATCH   64
#define I_DIM   4
#define H_DIM   1024
#define O_DIM   2
#define P_DIM   16
#define HPT     4                 // h-rows per thread
#define NTHREADS 256              // H_DIM / HPT
#define NWARPS  (NTHREADS / 32)
#define NRED    18                // 16 z-values + 2 y-values
#define PROW    36                // 32 z-partial cols + 4 y-partial cols

__device__ __forceinline__ float fast_tanh(float x) {
    float r;
    asm("tanh.approx.f32 %0, %1;" : "=f"(r) : "f"(x));
    return r;
}
__device__ __forceinline__ float shfl_xor_f(float v, int off) {
    return __shfl_xor_sync(0xffffffffu, v, off);
}

__global__ __launch_bounds__(NTHREADS, 1)
void rate_rnn_kernel(const float* __restrict__ x,     // (T,B,I,1)
                     const float* __restrict__ Win,   // (H,I)
                     const float* __restrict__ Wout,  // (O,H)
                     const float* __restrict__ pin,   // (H,P)
                     const float* __restrict__ pout,  // (H,P)
                     const float* __restrict__ l,     // (P,)
                     float* __restrict__ y)           // (T,B,O,1)
{
    const int b    = blockIdx.x;
    const int tid  = threadIdx.x;
    const int lane = tid & 31;
    const int warp = tid >> 5;

    __shared__ __align__(16) float pbuf[NWARPS][PROW];  // per-warp partials
    __shared__ __align__(16) float zbuf[P_DIM];         // broadcast z

    const float lm = 0.95122942450071400910f;  // exp(-DT/TAUM) = exp(-0.05)
    const float om = 1.0f - lm;

    // butterfly lane roles
    const bool hi16 = (lane & 16) != 0;
    const bool hi8  = (lane & 8)  != 0;
    const bool hi4  = (lane & 4)  != 0;
    const bool hi2  = (lane & 2)  != 0;
    const bool wyp  = (lane & 15) < 2;            // y-partial writer lanes 0,1,16,17
    const int  ycol = 32 + ((lane >> 4) << 1) + (lane & 1);  // y-partial column

    float lvec[P_DIM];
    #pragma unroll
    for (int p = 0; p < P_DIM; p++) lvec[p] = l[p];

    float mem[HPT];
    float win[HPT][I_DIM];     // om * Win (folded)
    float m[HPT][NRED];        // [pout (16) | Wout^T (2)]
    float lp[HPT][P_DIM];      // om * l * pin (folded)

    #pragma unroll
    for (int k = 0; k < HPT; k++) {
        const int h = tid + k * NTHREADS;
        mem[k] = 0.0f;
        #pragma unroll
        for (int i = 0; i < I_DIM; i++) win[k][i] = om * Win[h * I_DIM + i];
        #pragma unroll
        for (int p = 0; p < P_DIM; p++) {
            m[k][p]  = pout[h * P_DIM + p];
            lp[k][p] = om * lvec[p] * pin[h * P_DIM + p];
        }
        m[k][16] = Wout[h];           // Wout[0][h]
        m[k][17] = Wout[H_DIM + h];   // Wout[1][h]
    }

    const float4* xp = reinterpret_cast<const float4*>(x) + b;
    float4 xc = __ldg(xp);   // t = 0
    float4 xn = xc;

    // Iteration t: r_t = tanh(mem_t); y[t-1] = Wout.r_t; advance mem (t < T).
    for (int t = 0; t <= T_STEPS; t++) {
        {   // clamped prefetch of next x
            int tn = t + 1; if (tn > T_STEPS - 1) tn = T_STEPS - 1;
            xn = __ldg(xp + tn * BATCH);
        }

        // ---- phase 1: tanh + local accumulation (tanh/FMA interleaved) ----
        float part[NRED];
        #pragma unroll
        for (int j = 0; j < NRED; j++) part[j] = 0.0f;

        #pragma unroll
        for (int k = 0; k < HPT; k++) {
            const float r = fast_tanh(mem[k]);
            #pragma unroll
            for (int j = 0; j < NRED; j++)
                part[j] = fmaf(r, m[k][j], part[j]);
        }

        // ---- z-independent drive, hoisted off the post-bar2 chain ----
        float a0r[HPT];
        #pragma unroll
        for (int k = 0; k < HPT; k++) {
            float a = lm * mem[k];
            a = fmaf(win[k][0], xc.x, a);
            a = fmaf(win[k][1], xc.y, a);
            a = fmaf(win[k][2], xc.z, a);
            a = fmaf(win[k][3], xc.w, a);
            a0r[k] = a;
        }

        // ---- split-butterfly z: rounds 16/8/4/2 (4 deep, no final xor-1) ----
        float v8[8];
        #pragma unroll
        for (int i = 0; i < 8; i++) {
            float send = hi16 ? part[i] : part[i + 8];
            float keep = hi16 ? part[i + 8] : part[i];
            v8[i] = keep + shfl_xor_f(send, 16);
        }
        float v4[4];
        #pragma unroll
        for (int i = 0; i < 4; i++) {
            float send = hi8 ? v8[i] : v8[i + 4];
            float keep = hi8 ? v8[i + 4] : v8[i];
            v4[i] = keep + shfl_xor_f(send, 8);
        }
        float v2[2];
        #pragma unroll
        for (int i = 0; i < 2; i++) {
            float send = hi4 ? v4[i] : v4[i + 2];
            float keep = hi4 ? v4[i + 2] : v4[i];
            v2[i] = keep + shfl_xor_f(send, 4);
        }
        float v1;
        {
            float send = hi2 ? v2[0] : v2[1];
            float keep = hi2 ? v2[1] : v2[0];
            v1 = keep + shfl_xor_f(send, 2);
        }
        // lanes 2j,2j+1 hold the two partials of z[j]

        // ---- y: split + rounds 8/4/2 (4 deep, no final xor-1) ----
        float wv;
        {
            float send = hi16 ? part[16] : part[17];
            float keep = hi16 ? part[17] : part[16];
            wv = keep + shfl_xor_f(send, 16);
        }
        wv += shfl_xor_f(wv, 8);
        wv += shfl_xor_f(wv, 4);
        wv += shfl_xor_f(wv, 2);
        // lane L holds mod-2-class partial of y[16+(L>>4)]

        pbuf[warp][lane] = v1;            // 32 z-partial cols, coalesced
        if (wyp) pbuf[warp][ycol] = wv;   // lanes 0,1,16,17 -> cols 32..35
        __syncthreads();

        // ---- phase 2: sum 16 partials per value (8 float2 loads + tree) ----
        if (tid < NRED) {
            const int c = (tid < P_DIM) ? (2 * tid) : (32 + 2 * (tid - P_DIM));
            float2 q0 = *reinterpret_cast<const float2*>(&pbuf[0][c]);
            float2 q1 = *reinterpret_cast<const float2*>(&pbuf[1][c]);
            float2 q2 = *reinterpret_cast<const float2*>(&pbuf[2][c]);
            float2 q3 = *reinterpret_cast<const float2*>(&pbuf[3][c]);
            float2 q4 = *reinterpret_cast<const float2*>(&pbuf[4][c]);
            float2 q5 = *reinterpret_cast<const float2*>(&pbuf[5][c]);
            float2 q6 = *reinterpret_cast<const float2*>(&pbuf[6][c]);
            float2 q7 = *reinterpret_cast<const float2*>(&pbuf[7][c]);
            float sx = ((q0.x + q1.x) + (q2.x + q3.x)) + ((q4.x + q5.x) + (q6.x + q7.x));
            float sy = ((q0.y + q1.y) + (q2.y + q3.y)) + ((q4.y + q5.y) + (q6.y + q7.y));
            float s  = sx + sy;
            if (tid < P_DIM) {
                zbuf[tid] = s;
            } else if (t > 0) {
                y[((t - 1) * BATCH + b) * O_DIM + (tid - P_DIM)] = s;
            }
        }
        __syncthreads();

        if (t == T_STEPS) break;

        // ---- phase 3: z feedback only (drive already in a0r) ----
        const float4* zv = reinterpret_cast<const float4*>(zbuf);
        const float4 z0 = zv[0], z1 = zv[1], z2 = zv[2], z3 = zv[3];

        #pragma unroll
        for (int k = 0; k < HPT; k++) {
            float a1 = z0.x * lp[k][0];
            a1 = fmaf(z0.y, lp[k][1],  a1);
            a1 = fmaf(z0.z, lp[k][2],  a1);
            a1 = fmaf(z0.w, lp[k][3],  a1);
            a1 = fmaf(z1.x, lp[k][4],  a1);
            a1 = fmaf(z1.y, lp[k][5],  a1);
            a1 = fmaf(z1.z, lp[k][6],  a1);
            a1 = fmaf(z1.w, lp[k][7],  a1);

            float a2 = z2.x * lp[k][8];
            a2 = fmaf(z2.y, lp[k][9],  a2);
            a2 = fmaf(z2.z, lp[k][10], a2);
            a2 = fmaf(z2.w, lp[k][11], a2);
            a2 = fmaf(z3.x, lp[k][12], a2);
            a2 = fmaf(z3.y, lp[k][13], a2);
            a2 = fmaf(z3.z, lp[k][14], a2);
            a2 = fmaf(z3.w, lp[k][15], a2);

            mem[k] = a0r[k] + (a1 + a2);
        }
        xc = xn;
    }
}

extern "C" void kernel_launch(void* const* d_in, const int* in_sizes, int n_in,
                              void* d_out, int out_size)
{
    const float* x    = (const float*)d_in[0];
    const float* Win  = (const float*)d_in[1];
    const float* Wout = (const float*)d_in[2];
    const float* pin  = (const float*)d_in[3];
    const float* pout = (const float*)d_in[4];
    const float* l    = (const float*)d_in[5];
    float* y = (float*)d_out;

    rate_rnn_kernel<<<BATCH, NTHREADS>>>(x, Win, Wout, pin, pout, l, y);
}